// round 10
// baseline (speedup 1.0000x reference)
#include <cuda_runtime.h>
#include <cuda_bf16.h>
#include <cstdint>
#include <cstddef>

#define DD 128
#define VMAX 100000

// ---------------------------------------------------------------------------
// Global scratch (no allocs allowed)
// ---------------------------------------------------------------------------
__device__ float g_Y[2u * VMAX * DD];                    // Y_in | Y_out, fp32
__device__ float g_stats[2 * DD];                        // BN sum / sumsq
// W images: 12 chunks (in k0..3 | out k0..3 | loop k0..3), each [128 n][32 k] bf16
__device__ __align__(16) unsigned char g_Bhi[12 * 8192];
__device__ __align__(16) unsigned char g_Blo[12 * 8192];

// ---------------------------------------------------------------------------
// PTX helpers (generic-target safe: ldmatrix + mma.sync + cp.async)
// ---------------------------------------------------------------------------
__device__ __forceinline__ uint32_t smem_u32(const void* p) {
    uint32_t a;
    asm("{ .reg .u64 t; cvta.to.shared.u64 t, %1; cvt.u32.u64 %0, t; }" : "=r"(a) : "l"(p));
    return a;
}

#define LDSM4(r, addr)                                                          \
    asm volatile("ldmatrix.sync.aligned.m8n8.x4.shared.b16 {%0,%1,%2,%3}, [%4];" \
        : "=r"((r)[0]), "=r"((r)[1]), "=r"((r)[2]), "=r"((r)[3]) : "r"(addr))

#define MMA16816(d, a, b0, b1)                                                  \
    asm volatile("mma.sync.aligned.m16n8k16.row.col.f32.bf16.bf16.f32 "         \
        "{%0,%1,%2,%3}, {%4,%5,%6,%7}, {%8,%9}, {%0,%1,%2,%3};"                 \
        : "+f"((d)[0]), "+f"((d)[1]), "+f"((d)[2]), "+f"((d)[3])                \
        : "r"((a)[0]), "r"((a)[1]), "r"((a)[2]), "r"((a)[3]), "r"(b0), "r"(b1))

#define CP_ASYNC16(saddr, gptr)                                                 \
    asm volatile("cp.async.cg.shared.global [%0], [%1], 16;"                    \
        :: "r"(saddr), "l"(gptr) : "memory")
#define CP_ASYNC16Z(saddr, gptr, sz)                                            \
    asm volatile("cp.async.cg.shared.global [%0], [%1], 16, %2;"                \
        :: "r"(saddr), "l"(gptr), "r"(sz) : "memory")
#define CP_COMMIT()  asm volatile("cp.async.commit_group;" ::: "memory")
#define CP_WAIT0()   asm volatile("cp.async.wait_group 0;" ::: "memory")

// Truncation split: hi = upper-16 bits of fp32 (bf16-trunc), lo = bf16-trunc(z - hi).
__device__ __forceinline__ void split4(const float4 z, uint2& hi, uint2& lo) {
    uint32_t ux = __float_as_uint(z.x), uy = __float_as_uint(z.y);
    uint32_t uz = __float_as_uint(z.z), uw = __float_as_uint(z.w);
    float lx = z.x - __uint_as_float(ux & 0xFFFF0000u);
    float ly = z.y - __uint_as_float(uy & 0xFFFF0000u);
    float lz = z.z - __uint_as_float(uz & 0xFFFF0000u);
    float lw = z.w - __uint_as_float(uw & 0xFFFF0000u);
    hi.x = __byte_perm(ux, uy, 0x7632);
    hi.y = __byte_perm(uz, uw, 0x7632);
    lo.x = __byte_perm(__float_as_uint(lx), __float_as_uint(ly), 0x7632);
    lo.y = __byte_perm(__float_as_uint(lz), __float_as_uint(lw), 0x7632);
}

// ---------------------------------------------------------------------------
// Kernel 0: pre-split W into bf16 hi/lo chunk images, [n][k] rows of 32 bf16.
// ---------------------------------------------------------------------------
__global__ void prep_w(const float* __restrict__ in_w, const float* __restrict__ out_w,
                       const float* __restrict__ loop_w) {
    int c = blockIdx.x;
    const float* W = (c < 4) ? in_w : (c < 8 ? out_w : loop_w);
    int k0 = (c & 3) * 32;
    unsigned short* bh = reinterpret_cast<unsigned short*>(g_Bhi + c * 8192);
    unsigned short* bl = reinterpret_cast<unsigned short*>(g_Blo + c * 8192);
    for (int i = threadIdx.x; i < 4096; i += blockDim.x) {
        int n = i >> 5, k = i & 31;
        float v = W[(size_t)(k0 + k) * DD + n];
        uint32_t u = __float_as_uint(v);
        float lf = v - __uint_as_float(u & 0xFFFF0000u);
        bh[n * 32 + k] = (unsigned short)(u >> 16);
        bl[n * 32 + k] = (unsigned short)(__float_as_uint(lf) >> 16);
    }
}

// ---------------------------------------------------------------------------
// Kernel 1: per-edge scatter for ONE direction.  yb[dst] += norm*(x[src]*rel[et])
// ---------------------------------------------------------------------------
__global__ void edge_kernel(const float* __restrict__ x,
                            const float* __restrict__ rel,
                            const float* __restrict__ enorm,
                            const int* __restrict__ src,
                            const int* __restrict__ dst,
                            const int* __restrict__ et,
                            int n_edges,
                            float* __restrict__ yb) {
    int e = (blockIdx.x * blockDim.x + threadIdx.x) >> 5;
    if (e >= n_edges) return;
    int lane = threadIdx.x & 31;

    int   s = __ldg(&src[e]);
    int   d = __ldg(&dst[e]);
    int   t = __ldg(&et[e]);
    float n = __ldg(&enorm[e]);

    float4 xv = __ldg(reinterpret_cast<const float4*>(x)   + (size_t)s * 32 + lane);
    float4 rv = __ldg(reinterpret_cast<const float4*>(rel) + (size_t)t * 32 + lane);

    float a = n * xv.x * rv.x;
    float b = n * xv.y * rv.y;
    float c = n * xv.z * rv.z;
    float w = n * xv.w * rv.w;

    float* yp = yb + (size_t)d * DD + lane * 4;
    asm volatile("red.global.add.v4.f32 [%0], {%1,%2,%3,%4};"
                 :: "l"(yp), "f"(a), "f"(b), "f"(c), "f"(w) : "memory");
}

// ---------------------------------------------------------------------------
// Kernel 2: mma.sync bf16 hi/lo GEMM, fully double-buffered smem pipeline.
// smem (dynamic, 98304 B):
//   OAH(s) = s*10240           Ah stages          [ 0     : 20480)
//   OAL(s) = 20480 + s*10240   Al stages          [20480  : 40960)
//   OBH(s) = 40960 + s*10240   Bh stages          [40960  : 61440)
//   OBL(s) = 61440 + s*10240   Bl stages          [61440  : 81920)
//   ARAW   = 81920             raw fp32 A (128x128B)  [81920 : 98304)
// Per chunk: cp.async(c+1) -> mma(stage s) -> wait -> split raw -> Ah/Al[s^1].
// ---------------------------------------------------------------------------
#define ROWB 80
#define OAH(s) ((s) * 10240)
#define OAL(s) (20480 + (s) * 10240)
#define OBH(s) (40960 + (s) * 10240)
#define OBL(s) (61440 + (s) * 10240)
#define ARAW   81920
#define SMEM_GEMM 98304

__global__ void __launch_bounds__(256, 2) gemm_mma(
    const float* __restrict__ x,
    const float* __restrict__ loop_rel,
    const float* __restrict__ bias,
    float* __restrict__ hout,
    int V) {

    extern __shared__ __align__(16) unsigned char sm[];
    const uint32_t sb = smem_u32(sm);

    const int tid  = threadIdx.x;
    const int wid  = tid >> 5;
    const int lane = tid & 31;
    const int wm   = wid & 3;    // 4 warps over M (32 rows each)
    const int wn   = wid >> 2;   // 2 warps over N (64 cols each)
    const int m0   = blockIdx.x * 128;

    float acc[2][8][4];
#pragma unroll
    for (int i = 0; i < 2; i++)
#pragma unroll
        for (int j = 0; j < 8; j++)
#pragma unroll
            for (int k = 0; k < 4; k++) acc[i][j][k] = 0.f;

    // ---- cp.async raw A chunk (fp32) into single staging buffer ----
    auto cpA = [&](int c) {
        const int k0 = (c & 3) * 32;
        const float* Ab = (c < 4) ? g_Y : (c < 8 ? g_Y + (size_t)V * DD : x);
#pragma unroll
        for (int j = 0; j < 4; j++) {
            int i = tid + j * 256;
            int r = i >> 3, g = i & 7;
            int v = m0 + r;
            uint32_t sz = (v < V) ? 16u : 0u;
            const float* src = Ab + (size_t)(v < V ? v : 0) * DD + k0 + g * 4;
            CP_ASYNC16Z(sb + ARAW + r * 128 + g * 16, src, sz);
        }
    };
    // ---- cp.async B chunk hi/lo into stage s ----
    auto cpB = [&](int c, int s) {
        const unsigned char* gh = g_Bhi + c * 8192;
        const unsigned char* gl = g_Blo + c * 8192;
#pragma unroll
        for (int j = 0; j < 2; j++) {
            int i = tid + j * 256;          // 0..511 16B-chunks
            int r = i >> 2, g = i & 3;
            CP_ASYNC16(sb + OBH(s) + r * ROWB + g * 16, gh + r * 64 + g * 16);
            CP_ASYNC16(sb + OBL(s) + r * ROWB + g * 16, gl + r * 64 + g * 16);
        }
    };
    // ---- split raw -> Ah/Al stage s (same thread wrote the raw data) ----
    auto splitA = [&](int c, int s) {
        const bool is_loop = (c >= 8);
        const int k0 = (c & 3) * 32;
#pragma unroll
        for (int j = 0; j < 4; j++) {
            int i = tid + j * 256;
            int r = i >> 3, g = i & 7;
            float4 z = *reinterpret_cast<const float4*>(sm + ARAW + r * 128 + g * 16);
            if (is_loop) {
                float4 lr = __ldg(reinterpret_cast<const float4*>(loop_rel + k0 + g * 4));
                z.x *= lr.x; z.y *= lr.y; z.z *= lr.z; z.w *= lr.w;
            }
            uint2 hi, lo;
            split4(z, hi, lo);
            *reinterpret_cast<uint2*>(sm + OAH(s) + r * ROWB + g * 8) = hi;
            *reinterpret_cast<uint2*>(sm + OAL(s) + r * ROWB + g * 8) = lo;
        }
    };

    // ---- prologue: chunk 0 into stage 0 ----
    cpA(0);
    cpB(0, 0);
    CP_COMMIT();
    CP_WAIT0();
    __syncthreads();
    splitA(0, 0);
    __syncthreads();

    for (int c = 0; c < 12; c++) {
        const int s = c & 1;
        if (c < 11) {              // prefetch chunk c+1 while mma runs
            cpB(c + 1, s ^ 1);
            cpA(c + 1);
            CP_COMMIT();
        }

        // ---- mma over 2 K16 steps on stage s; pass order hh, lh, hl ----
#pragma unroll
        for (int k16 = 0; k16 < 2; k16++) {
            const uint32_t kb = k16 * 32 + ((lane >> 4) << 4);
            const uint32_t arow = (uint32_t)(wm * 32 + (lane & 15)) * ROWB + kb;
            const uint32_t brow = (uint32_t)(wn * 64 + (lane & 15)) * ROWB + kb;

            uint32_t ah[2][4], al[2][4], bb[4][4];
#pragma unroll
            for (int mt = 0; mt < 2; mt++) LDSM4(ah[mt], sb + OAH(s) + arow + mt * 16 * ROWB);
#pragma unroll
            for (int nb = 0; nb < 4; nb++) LDSM4(bb[nb], sb + OBH(s) + brow + nb * 16 * ROWB);
#pragma unroll
            for (int mt = 0; mt < 2; mt++)
#pragma unroll
                for (int nb = 0; nb < 4; nb++) {
                    MMA16816(acc[mt][nb * 2 + 0], ah[mt], bb[nb][0], bb[nb][2]);
                    MMA16816(acc[mt][nb * 2 + 1], ah[mt], bb[nb][1], bb[nb][3]);
                }
#pragma unroll
            for (int mt = 0; mt < 2; mt++) LDSM4(al[mt], sb + OAL(s) + arow + mt * 16 * ROWB);
#pragma unroll
            for (int mt = 0; mt < 2; mt++)
#pragma unroll
                for (int nb = 0; nb < 4; nb++) {
                    MMA16816(acc[mt][nb * 2 + 0], al[mt], bb[nb][0], bb[nb][2]);
                    MMA16816(acc[mt][nb * 2 + 1], al[mt], bb[nb][1], bb[nb][3]);
                }
#pragma unroll
            for (int nb = 0; nb < 4; nb++) LDSM4(bb[nb], sb + OBL(s) + brow + nb * 16 * ROWB);
#pragma unroll
            for (int mt = 0; mt < 2; mt++)
#pragma unroll
                for (int nb = 0; nb < 4; nb++) {
                    MMA16816(acc[mt][nb * 2 + 0], ah[mt], bb[nb][0], bb[nb][2]);
                    MMA16816(acc[mt][nb * 2 + 1], ah[mt], bb[nb][1], bb[nb][3]);
                }
        }

        if (c < 11) {
            CP_WAIT0();            // raw A + B for c+1 landed
            splitA(c + 1, s ^ 1);  // short; only tensor-idle window
        }
        __syncthreads();
    }

    // ---- epilogue: /3 + bias, store h, accumulate BN stats ----
    const float third = 1.f / 3.f;
    float ssum[16], ssq[16];
#pragma unroll
    for (int i = 0; i < 16; i++) { ssum[i] = 0.f; ssq[i] = 0.f; }

#pragma unroll
    for (int mt = 0; mt < 2; mt++) {
        int rowa = m0 + wm * 32 + mt * 16 + (lane >> 2);
        int rowb = rowa + 8;
#pragma unroll
        for (int nt = 0; nt < 8; nt++) {
            int col = wn * 64 + nt * 8 + (lane & 3) * 2;
            float2 bv = *reinterpret_cast<const float2*>(bias + col);
            float h0 = acc[mt][nt][0] * third + bv.x;
            float h1 = acc[mt][nt][1] * third + bv.y;
            float h2 = acc[mt][nt][2] * third + bv.x;
            float h3 = acc[mt][nt][3] * third + bv.y;
            if (rowa < V) {
                *reinterpret_cast<float2*>(hout + (size_t)rowa * DD + col) =
                    make_float2(h0, h1);
                ssum[nt * 2 + 0] += h0; ssq[nt * 2 + 0] += h0 * h0;
                ssum[nt * 2 + 1] += h1; ssq[nt * 2 + 1] += h1 * h1;
            }
            if (rowb < V) {
                *reinterpret_cast<float2*>(hout + (size_t)rowb * DD + col) =
                    make_float2(h2, h3);
                ssum[nt * 2 + 0] += h2; ssq[nt * 2 + 0] += h2 * h2;
                ssum[nt * 2 + 1] += h3; ssq[nt * 2 + 1] += h3 * h3;
            }
        }
    }
    // reduce over lane bits 2..4 (rows within warp)
#pragma unroll
    for (int i = 0; i < 16; i++) {
#pragma unroll
        for (int off = 4; off <= 16; off <<= 1) {
            ssum[i] += __shfl_xor_sync(0xFFFFFFFFu, ssum[i], off);
            ssq[i]  += __shfl_xor_sync(0xFFFFFFFFu, ssq[i],  off);
        }
    }
    __syncthreads();  // smem reuse
    float* Ssum = reinterpret_cast<float*>(sm);          // [8][128]
    float* Ssq  = reinterpret_cast<float*>(sm + 4096);   // [8][128]
#pragma unroll
    for (int j = 0; j < 4; j++) { Ssum[tid + j * 256] = 0.f; Ssq[tid + j * 256] = 0.f; }
    __syncthreads();
    if (lane < 4) {
#pragma unroll
        for (int nt = 0; nt < 8; nt++) {
            int col = wn * 64 + nt * 8 + lane * 2;
            Ssum[wid * 128 + col]     = ssum[nt * 2 + 0];
            Ssum[wid * 128 + col + 1] = ssum[nt * 2 + 1];
            Ssq [wid * 128 + col]     = ssq[nt * 2 + 0];
            Ssq [wid * 128 + col + 1] = ssq[nt * 2 + 1];
        }
    }
    __syncthreads();
    if (tid < 128) {
        float a = 0.f, b = 0.f;
#pragma unroll
        for (int w = 0; w < 8; w++) { a += Ssum[w * 128 + tid]; b += Ssq[w * 128 + tid]; }
        atomicAdd(&g_stats[tid],       a);
        atomicAdd(&g_stats[128 + tid], b);
    }
}

// ---------------------------------------------------------------------------
// Kernel 3: BatchNorm + ReLU, in place on h
// ---------------------------------------------------------------------------
__global__ void bn_kernel(float* __restrict__ h, int V) {
    __shared__ float ms[128];
    __shared__ float rs[128];
    if (threadIdx.x < 128) {
        float invn = 1.f / (float)V;
        float s  = g_stats[threadIdx.x];
        float sq = g_stats[128 + threadIdx.x];
        float m  = s * invn;
        float var = sq * invn - m * m;
        ms[threadIdx.x] = m;
        rs[threadIdx.x] = rsqrtf(var + 1e-5f);
    }
    __syncthreads();
    size_t total = (size_t)V * 32;
    float4* h4 = reinterpret_cast<float4*>(h);
    for (size_t i = (size_t)blockIdx.x * blockDim.x + threadIdx.x; i < total;
         i += (size_t)gridDim.x * blockDim.x) {
        int c4 = (int)(i & 31) * 4;
        float4 hv = h4[i];
        hv.x = fmaxf((hv.x - ms[c4 + 0]) * rs[c4 + 0], 0.f);
        hv.y = fmaxf((hv.y - ms[c4 + 1]) * rs[c4 + 1], 0.f);
        hv.z = fmaxf((hv.z - ms[c4 + 2]) * rs[c4 + 2], 0.f);
        hv.w = fmaxf((hv.w - ms[c4 + 3]) * rs[c4 + 3], 0.f);
        h4[i] = hv;
    }
}

// ---------------------------------------------------------------------------
// Kernel 4: rel_repr @ w_rel, 4 rel rows per block
// ---------------------------------------------------------------------------
__global__ void relw_kernel(const float* __restrict__ rel,
                            const float* __restrict__ w_rel,
                            float* __restrict__ out, int R) {
    __shared__ float rr[4][128];
    int r0 = blockIdx.x * 4;
    int c = threadIdx.x;
#pragma unroll
    for (int j = 0; j < 4; j++)
        rr[j][c] = (r0 + j < R) ? rel[(size_t)(r0 + j) * DD + c] : 0.f;
    __syncthreads();
    float a0 = 0.f, a1 = 0.f, a2 = 0.f, a3 = 0.f;
#pragma unroll 4
    for (int k = 0; k < 128; k++) {
        float w = __ldg(&w_rel[(size_t)k * DD + c]);
        a0 += rr[0][k] * w;
        a1 += rr[1][k] * w;
        a2 += rr[2][k] * w;
        a3 += rr[3][k] * w;
    }
    if (r0 + 0 < R) out[(size_t)(r0 + 0) * DD + c] = a0;
    if (r0 + 1 < R) out[(size_t)(r0 + 1) * DD + c] = a1;
    if (r0 + 2 < R) out[(size_t)(r0 + 2) * DD + c] = a2;
    if (r0 + 3 < R) out[(size_t)(r0 + 3) * DD + c] = a3;
}

// ---------------------------------------------------------------------------
extern "C" void kernel_launch(void* const* d_in, const int* in_sizes, int n_in,
                              void* d_out, int out_size) {
    const float* x        = (const float*)d_in[0];
    const float* rel      = (const float*)d_in[1];
    const float* enorm    = (const float*)d_in[2];
    const float* in_w     = (const float*)d_in[3];
    const float* out_w    = (const float*)d_in[4];
    const float* loop_w   = (const float*)d_in[5];
    const float* w_rel    = (const float*)d_in[6];
    const float* loop_rel = (const float*)d_in[7];
    const float* bias     = (const float*)d_in[8];
    const int*   src      = (const int*)d_in[9];
    const int*   dst      = (const int*)d_in[10];
    const int*   et       = (const int*)d_in[11];

    int V = in_sizes[0] / DD;
    int R = in_sizes[1] / DD;
    int E = in_sizes[2];
    int half = E / 2;

    float* h    = (float*)d_out;
    float* out2 = h + (size_t)V * DD;

    void* yptr = nullptr; void* sptr = nullptr;
    cudaGetSymbolAddress(&yptr, g_Y);
    cudaGetSymbolAddress(&sptr, g_stats);
    float* Yin  = (float*)yptr;
    float* Yout = Yin + (size_t)V * DD;
    cudaMemsetAsync(yptr, 0, (size_t)2 * V * DD * sizeof(float), 0);
    cudaMemsetAsync(sptr, 0, 2 * DD * sizeof(float), 0);

    cudaFuncSetAttribute(gemm_mma, cudaFuncAttributeMaxDynamicSharedMemorySize,
                         SMEM_GEMM);

    prep_w<<<12, 256>>>(in_w, out_w, loop_w);
    // two passes: per-launch working set (x + half of Y) fits in L2
    edge_kernel<<<(half + 7) / 8, 256>>>(x, rel, enorm, src, dst, et, half, Yin);
    edge_kernel<<<(E - half + 7) / 8, 256>>>(x, rel, enorm + half, src + half,
                                             dst + half, et + half, E - half, Yout);
    gemm_mma<<<(V + 127) / 128, 256, SMEM_GEMM>>>(x, loop_rel, bias, h, V);
    bn_kernel<<<1024, 256>>>(h, V);
    relw_kernel<<<(R + 3) / 4, 128>>>(rel, w_rel, out2, R);
}

// round 11
// speedup vs baseline: 1.1175x; 1.1175x over previous
#include <cuda_runtime.h>
#include <cuda_fp16.h>
#include <cstdint>
#include <cstddef>

#define DD 128
#define VMAX 100000

// ---------------------------------------------------------------------------
// Global scratch (no allocs allowed)
// ---------------------------------------------------------------------------
__device__ float g_Y[2u * VMAX * DD];                    // Y_in | Y_out, fp32
__device__ float g_stats[2 * DD];                        // BN sum / sumsq
// W image: 12 chunks (in k0..3 | out k0..3 | loop' k0..3), each [128 n][32 k] fp16
__device__ __align__(16) unsigned char g_Bh[12 * 8192];

// ---------------------------------------------------------------------------
// PTX helpers (generic-target safe: ldmatrix + mma.sync + cp.async)
// ---------------------------------------------------------------------------
__device__ __forceinline__ uint32_t smem_u32(const void* p) {
    uint32_t a;
    asm("{ .reg .u64 t; cvta.to.shared.u64 t, %1; cvt.u32.u64 %0, t; }" : "=r"(a) : "l"(p));
    return a;
}

#define LDSM4(r, addr)                                                          \
    asm volatile("ldmatrix.sync.aligned.m8n8.x4.shared.b16 {%0,%1,%2,%3}, [%4];" \
        : "=r"((r)[0]), "=r"((r)[1]), "=r"((r)[2]), "=r"((r)[3]) : "r"(addr))

#define MMA16816F16(d, a, b0, b1)                                               \
    asm volatile("mma.sync.aligned.m16n8k16.row.col.f32.f16.f16.f32 "           \
        "{%0,%1,%2,%3}, {%4,%5,%6,%7}, {%8,%9}, {%0,%1,%2,%3};"                 \
        : "+f"((d)[0]), "+f"((d)[1]), "+f"((d)[2]), "+f"((d)[3])                \
        : "r"((a)[0]), "r"((a)[1]), "r"((a)[2]), "r"((a)[3]), "r"(b0), "r"(b1))

#define CP_ASYNC16(saddr, gptr)                                                 \
    asm volatile("cp.async.cg.shared.global [%0], [%1], 16;"                    \
        :: "r"(saddr), "l"(gptr) : "memory")
#define CP_COMMIT()  asm volatile("cp.async.commit_group;" ::: "memory")
#define CP_WAIT0()   asm volatile("cp.async.wait_group 0;" ::: "memory")

// fp16 split: hi = rn(z), lo = rn(z - hi).  A ≈ hi + lo with residual ~2^-22.
__device__ __forceinline__ void split4h(const float4 z, uint2& hi, uint2& lo) {
    __half2 h01 = __floats2half2_rn(z.x, z.y);
    __half2 h23 = __floats2half2_rn(z.z, z.w);
    float2 f01 = __half22float2(h01);
    float2 f23 = __half22float2(h23);
    __half2 l01 = __floats2half2_rn(z.x - f01.x, z.y - f01.y);
    __half2 l23 = __floats2half2_rn(z.z - f23.x, z.w - f23.y);
    hi.x = *reinterpret_cast<uint32_t*>(&h01);
    hi.y = *reinterpret_cast<uint32_t*>(&h23);
    lo.x = *reinterpret_cast<uint32_t*>(&l01);
    lo.y = *reinterpret_cast<uint32_t*>(&l23);
}

// ---------------------------------------------------------------------------
// Kernel 0: W image, fp16, [n][k] rows of 32. loop_rel folded into loop_w.
// chunk c: W = {in,out,loop}[c/4], k0 = (c%4)*32.  B[n][k] = W'[(k0+k)*128+n]
// ---------------------------------------------------------------------------
__global__ void prep_w(const float* __restrict__ in_w, const float* __restrict__ out_w,
                       const float* __restrict__ loop_w,
                       const float* __restrict__ loop_rel) {
    int c = blockIdx.x;
    const float* W = (c < 4) ? in_w : (c < 8 ? out_w : loop_w);
    int k0 = (c & 3) * 32;
    __half* bh = reinterpret_cast<__half*>(g_Bh + c * 8192);
    for (int i = threadIdx.x; i < 4096; i += blockDim.x) {
        int n = i >> 5, k = i & 31;
        float v = W[(size_t)(k0 + k) * DD + n];
        if (c >= 8) v *= loop_rel[k0 + k];   // exact fold: (x*lr)@W = x@(diag(lr)W)
        bh[n * 32 + k] = __float2half_rn(v);
    }
}

// ---------------------------------------------------------------------------
// Kernel 1: per-edge scatter for ONE direction.  yb[dst] += norm*(x[src]*rel[et])
// ---------------------------------------------------------------------------
__global__ void edge_kernel(const float* __restrict__ x,
                            const float* __restrict__ rel,
                            const float* __restrict__ enorm,
                            const int* __restrict__ src,
                            const int* __restrict__ dst,
                            const int* __restrict__ et,
                            int n_edges,
                            float* __restrict__ yb) {
    int e = (blockIdx.x * blockDim.x + threadIdx.x) >> 5;
    if (e >= n_edges) return;
    int lane = threadIdx.x & 31;

    int   s = __ldg(&src[e]);
    int   d = __ldg(&dst[e]);
    int   t = __ldg(&et[e]);
    float n = __ldg(&enorm[e]);

    float4 xv = __ldg(reinterpret_cast<const float4*>(x)   + (size_t)s * 32 + lane);
    float4 rv = __ldg(reinterpret_cast<const float4*>(rel) + (size_t)t * 32 + lane);

    float a = n * xv.x * rv.x;
    float b = n * xv.y * rv.y;
    float c = n * xv.z * rv.z;
    float w = n * xv.w * rv.w;

    float* yp = yb + (size_t)d * DD + lane * 4;
    asm volatile("red.global.add.v4.f32 [%0], {%1,%2,%3,%4};"
                 :: "l"(yp), "f"(a), "f"(b), "f"(c), "f"(w) : "memory");
}

// ---------------------------------------------------------------------------
// Kernel 2: mma.sync fp16 hi/lo GEMM — 2 passes: (Ahi+Alo)·Bhi.
//   h[v,:] = ( [Yin | Yout | x][v,:384] @ [in_w; out_w; diag(lr)loop_w] )/3 + bias
// CTA tile 128x128, 8 warps (warp tile 32x64), 12 K-chunks of 32.
// ---------------------------------------------------------------------------
#define ROWB 80   // bytes per smem row (64 B data + pad) — conflict-free ldmatrix

__global__ void __launch_bounds__(256, 2) gemm_mma(
    const float* __restrict__ x,
    const float* __restrict__ bias,
    float* __restrict__ hout,
    int V) {

    __shared__ __align__(16) unsigned char sAh[128 * ROWB];
    __shared__ __align__(16) unsigned char sAl[128 * ROWB];
    __shared__ __align__(16) unsigned char sBh[128 * ROWB];

    const uint32_t uAh = smem_u32(sAh);
    const uint32_t uAl = smem_u32(sAl);
    const uint32_t uBh = smem_u32(sBh);

    const int tid  = threadIdx.x;
    const int wid  = tid >> 5;
    const int lane = tid & 31;
    const int wm   = wid & 3;    // 4 warps over M (32 rows each)
    const int wn   = wid >> 2;   // 2 warps over N (64 cols each)
    const int m0   = blockIdx.x * 128;

    float acc[2][8][4];
#pragma unroll
    for (int i = 0; i < 2; i++)
#pragma unroll
        for (int j = 0; j < 8; j++)
#pragma unroll
            for (int k = 0; k < 4; k++) acc[i][j][k] = 0.f;

    for (int c = 0; c < 12; c++) {
        __syncthreads();
        // ---- B chunk via cp.async (8 KB) ----
        {
            const unsigned char* gh = g_Bh + c * 8192;
            for (int j = 0; j < 2; j++) {
                int i = tid + j * 256;          // 0..511 16B-chunks
                int r = i >> 2, g = i & 3;
                CP_ASYNC16(uBh + r * ROWB + g * 16, gh + r * 64 + g * 16);
            }
            CP_COMMIT();
        }
        // ---- load + fp16-split A chunk ----
        {
            const int k0 = (c & 3) * 32;
            const float* Ab = (c < 4) ? g_Y : (c < 8 ? g_Y + (size_t)V * DD : x);
#pragma unroll
            for (int j = 0; j < 4; j++) {
                int i = tid + j * 256;
                int r = i >> 3, g = i & 7;
                int v = m0 + r;
                float4 z = make_float4(0.f, 0.f, 0.f, 0.f);
                if (v < V)
                    z = *reinterpret_cast<const float4*>(Ab + (size_t)v * DD + k0 + g * 4);
                uint2 hi, lo;
                split4h(z, hi, lo);
                *reinterpret_cast<uint2*>(sAh + r * ROWB + g * 8) = hi;
                *reinterpret_cast<uint2*>(sAl + r * ROWB + g * 8) = lo;
            }
        }
        CP_WAIT0();
        __syncthreads();

        // ---- mma over 2 K16 steps; passes: Ahi*Bhi then Alo*Bhi ----
#pragma unroll
        for (int k16 = 0; k16 < 2; k16++) {
            const uint32_t kb = k16 * 32 + ((lane >> 4) << 4);
            const uint32_t arow = (uint32_t)(wm * 32 + (lane & 15)) * ROWB + kb;
            const uint32_t brow = (uint32_t)(wn * 64 + (lane & 15)) * ROWB + kb;

            uint32_t ah[2][4], al[2][4], bb[4][4];
#pragma unroll
            for (int mt = 0; mt < 2; mt++) LDSM4(ah[mt], uAh + arow + mt * 16 * ROWB);
#pragma unroll
            for (int nb = 0; nb < 4; nb++) LDSM4(bb[nb], uBh + brow + nb * 16 * ROWB);
#pragma unroll
            for (int mt = 0; mt < 2; mt++)
#pragma unroll
                for (int nb = 0; nb < 4; nb++) {
                    MMA16816F16(acc[mt][nb * 2 + 0], ah[mt], bb[nb][0], bb[nb][2]);
                    MMA16816F16(acc[mt][nb * 2 + 1], ah[mt], bb[nb][1], bb[nb][3]);
                }
#pragma unroll
            for (int mt = 0; mt < 2; mt++) LDSM4(al[mt], uAl + arow + mt * 16 * ROWB);
#pragma unroll
            for (int mt = 0; mt < 2; mt++)
#pragma unroll
                for (int nb = 0; nb < 4; nb++) {
                    MMA16816F16(acc[mt][nb * 2 + 0], al[mt], bb[nb][0], bb[nb][2]);
                    MMA16816F16(acc[mt][nb * 2 + 1], al[mt], bb[nb][1], bb[nb][3]);
                }
        }
    }

    // ---- epilogue: /3 + bias, store h, accumulate BN stats ----
    const float third = 1.f / 3.f;
    float ssum[16], ssq[16];
#pragma unroll
    for (int i = 0; i < 16; i++) { ssum[i] = 0.f; ssq[i] = 0.f; }

#pragma unroll
    for (int mt = 0; mt < 2; mt++) {
        int rowa = m0 + wm * 32 + mt * 16 + (lane >> 2);
        int rowb = rowa + 8;
#pragma unroll
        for (int nt = 0; nt < 8; nt++) {
            int col = wn * 64 + nt * 8 + (lane & 3) * 2;
            float2 bv = *reinterpret_cast<const float2*>(bias + col);
            float h0 = acc[mt][nt][0] * third + bv.x;
            float h1 = acc[mt][nt][1] * third + bv.y;
            float h2 = acc[mt][nt][2] * third + bv.x;
            float h3 = acc[mt][nt][3] * third + bv.y;
            if (rowa < V) {
                *reinterpret_cast<float2*>(hout + (size_t)rowa * DD + col) =
                    make_float2(h0, h1);
                ssum[nt * 2 + 0] += h0; ssq[nt * 2 + 0] += h0 * h0;
                ssum[nt * 2 + 1] += h1; ssq[nt * 2 + 1] += h1 * h1;
            }
            if (rowb < V) {
                *reinterpret_cast<float2*>(hout + (size_t)rowb * DD + col) =
                    make_float2(h2, h3);
                ssum[nt * 2 + 0] += h2; ssq[nt * 2 + 0] += h2 * h2;
                ssum[nt * 2 + 1] += h3; ssq[nt * 2 + 1] += h3 * h3;
            }
        }
    }
    // reduce over lane bits 2..4 (rows within warp)
#pragma unroll
    for (int i = 0; i < 16; i++) {
#pragma unroll
        for (int off = 4; off <= 16; off <<= 1) {
            ssum[i] += __shfl_xor_sync(0xFFFFFFFFu, ssum[i], off);
            ssq[i]  += __shfl_xor_sync(0xFFFFFFFFu, ssq[i],  off);
        }
    }
    __syncthreads();  // smem reuse
    float* Ssum = reinterpret_cast<float*>(sAh);   // [8][128]
    float* Ssq  = reinterpret_cast<float*>(sAl);   // [8][128]
#pragma unroll
    for (int j = 0; j < 4; j++) { Ssum[tid + j * 256] = 0.f; Ssq[tid + j * 256] = 0.f; }
    __syncthreads();
    if (lane < 4) {
#pragma unroll
        for (int nt = 0; nt < 8; nt++) {
            int col = wn * 64 + nt * 8 + lane * 2;
            Ssum[wid * 128 + col]     = ssum[nt * 2 + 0];
            Ssum[wid * 128 + col + 1] = ssum[nt * 2 + 1];
            Ssq [wid * 128 + col]     = ssq[nt * 2 + 0];
            Ssq [wid * 128 + col + 1] = ssq[nt * 2 + 1];
        }
    }
    __syncthreads();
    if (tid < 128) {
        float a = 0.f, b = 0.f;
#pragma unroll
        for (int w = 0; w < 8; w++) { a += Ssum[w * 128 + tid]; b += Ssq[w * 128 + tid]; }
        atomicAdd(&g_stats[tid],       a);
        atomicAdd(&g_stats[128 + tid], b);
    }
}

// ---------------------------------------------------------------------------
// Kernel 3: BatchNorm + ReLU, in place on h
// ---------------------------------------------------------------------------
__global__ void bn_kernel(float* __restrict__ h, int V) {
    __shared__ float ms[128];
    __shared__ float rs[128];
    if (threadIdx.x < 128) {
        float invn = 1.f / (float)V;
        float s  = g_stats[threadIdx.x];
        float sq = g_stats[128 + threadIdx.x];
        float m  = s * invn;
        float var = sq * invn - m * m;
        ms[threadIdx.x] = m;
        rs[threadIdx.x] = rsqrtf(var + 1e-5f);
    }
    __syncthreads();
    size_t total = (size_t)V * 32;
    float4* h4 = reinterpret_cast<float4*>(h);
    for (size_t i = (size_t)blockIdx.x * blockDim.x + threadIdx.x; i < total;
         i += (size_t)gridDim.x * blockDim.x) {
        int c4 = (int)(i & 31) * 4;
        float4 hv = h4[i];
        hv.x = fmaxf((hv.x - ms[c4 + 0]) * rs[c4 + 0], 0.f);
        hv.y = fmaxf((hv.y - ms[c4 + 1]) * rs[c4 + 1], 0.f);
        hv.z = fmaxf((hv.z - ms[c4 + 2]) * rs[c4 + 2], 0.f);
        hv.w = fmaxf((hv.w - ms[c4 + 3]) * rs[c4 + 3], 0.f);
        h4[i] = hv;
    }
}

// ---------------------------------------------------------------------------
// Kernel 4: rel_repr @ w_rel, 4 rel rows per block
// ---------------------------------------------------------------------------
__global__ void relw_kernel(const float* __restrict__ rel,
                            const float* __restrict__ w_rel,
                            float* __restrict__ out, int R) {
    __shared__ float rr[4][128];
    int r0 = blockIdx.x * 4;
    int c = threadIdx.x;
#pragma unroll
    for (int j = 0; j < 4; j++)
        rr[j][c] = (r0 + j < R) ? rel[(size_t)(r0 + j) * DD + c] : 0.f;
    __syncthreads();
    float a0 = 0.f, a1 = 0.f, a2 = 0.f, a3 = 0.f;
#pragma unroll 4
    for (int k = 0; k < 128; k++) {
        float w = __ldg(&w_rel[(size_t)k * DD + c]);
        a0 += rr[0][k] * w;
        a1 += rr[1][k] * w;
        a2 += rr[2][k] * w;
        a3 += rr[3][k] * w;
    }
    if (r0 + 0 < R) out[(size_t)(r0 + 0) * DD + c] = a0;
    if (r0 + 1 < R) out[(size_t)(r0 + 1) * DD + c] = a1;
    if (r0 + 2 < R) out[(size_t)(r0 + 2) * DD + c] = a2;
    if (r0 + 3 < R) out[(size_t)(r0 + 3) * DD + c] = a3;
}

// ---------------------------------------------------------------------------
extern "C" void kernel_launch(void* const* d_in, const int* in_sizes, int n_in,
                              void* d_out, int out_size) {
    const float* x        = (const float*)d_in[0];
    const float* rel      = (const float*)d_in[1];
    const float* enorm    = (const float*)d_in[2];
    const float* in_w     = (const float*)d_in[3];
    const float* out_w    = (const float*)d_in[4];
    const float* loop_w   = (const float*)d_in[5];
    const float* w_rel    = (const float*)d_in[6];
    const float* loop_rel = (const float*)d_in[7];
    const float* bias     = (const float*)d_in[8];
    const int*   src      = (const int*)d_in[9];
    const int*   dst      = (const int*)d_in[10];
    const int*   et       = (const int*)d_in[11];

    int V = in_sizes[0] / DD;
    int R = in_sizes[1] / DD;
    int E = in_sizes[2];
    int half = E / 2;

    float* h    = (float*)d_out;
    float* out2 = h + (size_t)V * DD;

    void* yptr = nullptr; void* sptr = nullptr;
    cudaGetSymbolAddress(&yptr, g_Y);
    cudaGetSymbolAddress(&sptr, g_stats);
    float* Yin  = (float*)yptr;
    float* Yout = Yin + (size_t)V * DD;
    cudaMemsetAsync(yptr, 0, (size_t)2 * V * DD * sizeof(float), 0);
    cudaMemsetAsync(sptr, 0, 2 * DD * sizeof(float), 0);

    prep_w<<<12, 256>>>(in_w, out_w, loop_w, loop_rel);
    // two passes: per-launch working set (x + half of Y) fits in L2
    edge_kernel<<<(half + 7) / 8, 256>>>(x, rel, enorm, src, dst, et, half, Yin);
    edge_kernel<<<(E - half + 7) / 8, 256>>>(x, rel, enorm + half, src + half,
                                             dst + half, et + half, E - half, Yout);
    gemm_mma<<<(V + 127) / 128, 256>>>(x, bias, h, V);
    bn_kernel<<<1024, 256>>>(h, V);
    relw_kernel<<<(R + 3) / 4, 128>>>(rel, w_rel, out2, R);
}

// round 12
// speedup vs baseline: 1.1324x; 1.0134x over previous
#include <cuda_runtime.h>
#include <cuda_fp16.h>
#include <cstdint>
#include <cstddef>

#define DD 128
#define VMAX 100000

// ---------------------------------------------------------------------------
// Global scratch (no allocs allowed)
// ---------------------------------------------------------------------------
__device__ float g_Y[2u * VMAX * DD];                    // Y_in | Y_out, fp32
__device__ float g_stats[2 * DD];                        // BN sum / sumsq
// W image: 6 chunks (in k0,k1 | out k0,k1 | loop' k0,k1), each [128 n][64 k] fp16
__device__ __align__(16) unsigned char g_Bh[6 * 16384];

// ---------------------------------------------------------------------------
// PTX helpers (generic-target safe: ldmatrix + mma.sync + cp.async)
// ---------------------------------------------------------------------------
__device__ __forceinline__ uint32_t smem_u32(const void* p) {
    uint32_t a;
    asm("{ .reg .u64 t; cvta.to.shared.u64 t, %1; cvt.u32.u64 %0, t; }" : "=r"(a) : "l"(p));
    return a;
}

#define LDSM4(r, addr)                                                          \
    asm volatile("ldmatrix.sync.aligned.m8n8.x4.shared.b16 {%0,%1,%2,%3}, [%4];" \
        : "=r"((r)[0]), "=r"((r)[1]), "=r"((r)[2]), "=r"((r)[3]) : "r"(addr))

#define MMA16816F16(d, a, b0, b1)                                               \
    asm volatile("mma.sync.aligned.m16n8k16.row.col.f32.f16.f16.f32 "           \
        "{%0,%1,%2,%3}, {%4,%5,%6,%7}, {%8,%9}, {%0,%1,%2,%3};"                 \
        : "+f"((d)[0]), "+f"((d)[1]), "+f"((d)[2]), "+f"((d)[3])                \
        : "r"((a)[0]), "r"((a)[1]), "r"((a)[2]), "r"((a)[3]), "r"(b0), "r"(b1))

#define CP_ASYNC16(saddr, gptr)                                                 \
    asm volatile("cp.async.cg.shared.global [%0], [%1], 16;"                    \
        :: "r"(saddr), "l"(gptr) : "memory")
#define CP_COMMIT()  asm volatile("cp.async.commit_group;" ::: "memory")
#define CP_WAIT0()   asm volatile("cp.async.wait_group 0;" ::: "memory")

// fp16 split: hi = rn(z), lo = rn(z - hi).  A ≈ hi + lo with residual ~2^-22.
__device__ __forceinline__ void split4h(const float4 z, uint2& hi, uint2& lo) {
    __half2 h01 = __floats2half2_rn(z.x, z.y);
    __half2 h23 = __floats2half2_rn(z.z, z.w);
    float2 f01 = __half22float2(h01);
    float2 f23 = __half22float2(h23);
    __half2 l01 = __floats2half2_rn(z.x - f01.x, z.y - f01.y);
    __half2 l23 = __floats2half2_rn(z.z - f23.x, z.w - f23.y);
    hi.x = *reinterpret_cast<uint32_t*>(&h01);
    hi.y = *reinterpret_cast<uint32_t*>(&h23);
    lo.x = *reinterpret_cast<uint32_t*>(&l01);
    lo.y = *reinterpret_cast<uint32_t*>(&l23);
}

// ---------------------------------------------------------------------------
// Kernel 0: W image, fp16, 6 chunks of [128 n][64 k]. loop_rel folded in.
// chunk c: W = {in,out,loop}[c/2], k0 = (c&1)*64.  B[n][k] = W'[(k0+k)*128+n]
// ---------------------------------------------------------------------------
__global__ void prep_w(const float* __restrict__ in_w, const float* __restrict__ out_w,
                       const float* __restrict__ loop_w,
                       const float* __restrict__ loop_rel) {
    int c = blockIdx.x;
    const float* W = (c < 2) ? in_w : (c < 4 ? out_w : loop_w);
    int k0 = (c & 1) * 64;
    __half* bh = reinterpret_cast<__half*>(g_Bh + c * 16384);
    for (int i = threadIdx.x; i < 8192; i += blockDim.x) {
        int n = i >> 6, k = i & 63;
        float v = W[(size_t)(k0 + k) * DD + n];
        if (c >= 4) v *= loop_rel[k0 + k];   // exact fold: (x*lr)@W = x@(diag(lr)W)
        bh[n * 64 + k] = __float2half_rn(v);
    }
}

// ---------------------------------------------------------------------------
// Kernel 1: per-edge scatter for ONE direction.  yb[dst] += norm*(x[src]*rel[et])
// ---------------------------------------------------------------------------
__global__ void edge_kernel(const float* __restrict__ x,
                            const float* __restrict__ rel,
                            const float* __restrict__ enorm,
                            const int* __restrict__ src,
                            const int* __restrict__ dst,
                            const int* __restrict__ et,
                            int n_edges,
                            float* __restrict__ yb) {
    int e = (blockIdx.x * blockDim.x + threadIdx.x) >> 5;
    if (e >= n_edges) return;
    int lane = threadIdx.x & 31;

    int   s = __ldg(&src[e]);
    int   d = __ldg(&dst[e]);
    int   t = __ldg(&et[e]);
    float n = __ldg(&enorm[e]);

    float4 xv = __ldg(reinterpret_cast<const float4*>(x)   + (size_t)s * 32 + lane);
    float4 rv = __ldg(reinterpret_cast<const float4*>(rel) + (size_t)t * 32 + lane);

    float a = n * xv.x * rv.x;
    float b = n * xv.y * rv.y;
    float c = n * xv.z * rv.z;
    float w = n * xv.w * rv.w;

    float* yp = yb + (size_t)d * DD + lane * 4;
    asm volatile("red.global.add.v4.f32 [%0], {%1,%2,%3,%4};"
                 :: "l"(yp), "f"(a), "f"(b), "f"(c), "f"(w) : "memory");
}

// ---------------------------------------------------------------------------
// Kernel 2: mma.sync fp16 hi/lo GEMM — 2 passes, K-chunks of 64 (6 iterations).
//   h[v,:] = ( [Yin | Yout | x][v,:384] @ [in_w; out_w; diag(lr)loop_w] )/3 + bias
// CTA tile 128x128, 8 warps (warp tile 32x64).
// smem (dynamic): Ah[0:18432) Al[18432:36864) Bh[36864:55296), rows of 144 B.
// ---------------------------------------------------------------------------
#define ROWB 144      // 128 B data (64 fp16) + 16 B pad -> conflict-free ldmatrix
#define OAH 0
#define OAL 18432
#define OBH 36864
#define SMEM_GEMM 55296

__global__ void __launch_bounds__(256, 2) gemm_mma(
    const float* __restrict__ x,
    const float* __restrict__ bias,
    float* __restrict__ hout,
    int V) {

    extern __shared__ __align__(16) unsigned char sm[];
    const uint32_t sb = smem_u32(sm);
    const uint32_t uAh = sb + OAH;
    const uint32_t uAl = sb + OAL;
    const uint32_t uBh = sb + OBH;

    const int tid  = threadIdx.x;
    const int wid  = tid >> 5;
    const int lane = tid & 31;
    const int wm   = wid & 3;    // 4 warps over M (32 rows each)
    const int wn   = wid >> 2;   // 2 warps over N (64 cols each)
    const int m0   = blockIdx.x * 128;

    float acc[2][8][4];
#pragma unroll
    for (int i = 0; i < 2; i++)
#pragma unroll
        for (int j = 0; j < 8; j++)
#pragma unroll
            for (int k = 0; k < 4; k++) acc[i][j][k] = 0.f;

    for (int c = 0; c < 6; c++) {
        __syncthreads();
        // ---- B chunk via cp.async (16 KB): 1024 16B pieces ----
        {
            const unsigned char* gh = g_Bh + c * 16384;
#pragma unroll
            for (int j = 0; j < 4; j++) {
                int i = tid + j * 256;          // 0..1023
                int r = i >> 3, g = i & 7;
                CP_ASYNC16(uBh + r * ROWB + g * 16, gh + r * 128 + g * 16);
            }
            CP_COMMIT();
        }
        // ---- load + fp16-split A chunk: 128 rows x 64 k fp32 ----
        {
            const int k0 = (c & 1) * 64;
            const float* Ab = (c < 2) ? g_Y : (c < 4 ? g_Y + (size_t)V * DD : x);
#pragma unroll
            for (int j = 0; j < 8; j++) {
                int i = tid + j * 256;          // 0..2047 float4 slots
                int r = i >> 4, g = i & 15;
                int v = m0 + r;
                float4 z = make_float4(0.f, 0.f, 0.f, 0.f);
                if (v < V)
                    z = *reinterpret_cast<const float4*>(Ab + (size_t)v * DD + k0 + g * 4);
                uint2 hi, lo;
                split4h(z, hi, lo);
                *reinterpret_cast<uint2*>(sm + OAH + r * ROWB + g * 8) = hi;
                *reinterpret_cast<uint2*>(sm + OAL + r * ROWB + g * 8) = lo;
            }
        }
        CP_WAIT0();
        __syncthreads();

        // ---- mma over 4 k16 steps; passes: Ahi*Bhi then Alo*Bhi ----
#pragma unroll
        for (int k16 = 0; k16 < 4; k16++) {
            const uint32_t kb = k16 * 32 + ((lane >> 4) << 4);
            const uint32_t arow = (uint32_t)(wm * 32 + (lane & 15)) * ROWB + kb;
            const uint32_t brow = (uint32_t)(wn * 64 + (lane & 15)) * ROWB + kb;

            uint32_t ah[2][4], al[2][4], bb[4][4];
#pragma unroll
            for (int mt = 0; mt < 2; mt++) LDSM4(ah[mt], uAh + arow + mt * 16 * ROWB);
#pragma unroll
            for (int nb = 0; nb < 4; nb++) LDSM4(bb[nb], uBh + brow + nb * 16 * ROWB);
#pragma unroll
            for (int mt = 0; mt < 2; mt++)
#pragma unroll
                for (int nb = 0; nb < 4; nb++) {
                    MMA16816F16(acc[mt][nb * 2 + 0], ah[mt], bb[nb][0], bb[nb][2]);
                    MMA16816F16(acc[mt][nb * 2 + 1], ah[mt], bb[nb][1], bb[nb][3]);
                }
#pragma unroll
            for (int mt = 0; mt < 2; mt++) LDSM4(al[mt], uAl + arow + mt * 16 * ROWB);
#pragma unroll
            for (int mt = 0; mt < 2; mt++)
#pragma unroll
                for (int nb = 0; nb < 4; nb++) {
                    MMA16816F16(acc[mt][nb * 2 + 0], al[mt], bb[nb][0], bb[nb][2]);
                    MMA16816F16(acc[mt][nb * 2 + 1], al[mt], bb[nb][1], bb[nb][3]);
                }
        }
    }

    // ---- epilogue: /3 + bias, store h, accumulate BN stats ----
    const float third = 1.f / 3.f;
    float ssum[16], ssq[16];
#pragma unroll
    for (int i = 0; i < 16; i++) { ssum[i] = 0.f; ssq[i] = 0.f; }

#pragma unroll
    for (int mt = 0; mt < 2; mt++) {
        int rowa = m0 + wm * 32 + mt * 16 + (lane >> 2);
        int rowb = rowa + 8;
#pragma unroll
        for (int nt = 0; nt < 8; nt++) {
            int col = wn * 64 + nt * 8 + (lane & 3) * 2;
            float2 bv = *reinterpret_cast<const float2*>(bias + col);
            float h0 = acc[mt][nt][0] * third + bv.x;
            float h1 = acc[mt][nt][1] * third + bv.y;
            float h2 = acc[mt][nt][2] * third + bv.x;
            float h3 = acc[mt][nt][3] * third + bv.y;
            if (rowa < V) {
                *reinterpret_cast<float2*>(hout + (size_t)rowa * DD + col) =
                    make_float2(h0, h1);
                ssum[nt * 2 + 0] += h0; ssq[nt * 2 + 0] += h0 * h0;
                ssum[nt * 2 + 1] += h1; ssq[nt * 2 + 1] += h1 * h1;
            }
            if (rowb < V) {
                *reinterpret_cast<float2*>(hout + (size_t)rowb * DD + col) =
                    make_float2(h2, h3);
                ssum[nt * 2 + 0] += h2; ssq[nt * 2 + 0] += h2 * h2;
                ssum[nt * 2 + 1] += h3; ssq[nt * 2 + 1] += h3 * h3;
            }
        }
    }
    // reduce over lane bits 2..4 (rows within warp)
#pragma unroll
    for (int i = 0; i < 16; i++) {
#pragma unroll
        for (int off = 4; off <= 16; off <<= 1) {
            ssum[i] += __shfl_xor_sync(0xFFFFFFFFu, ssum[i], off);
            ssq[i]  += __shfl_xor_sync(0xFFFFFFFFu, ssq[i],  off);
        }
    }
    __syncthreads();  // smem reuse
    float* Ssum = reinterpret_cast<float*>(sm);          // [8][128]
    float* Ssq  = reinterpret_cast<float*>(sm + 4096);   // [8][128]
#pragma unroll
    for (int j = 0; j < 4; j++) { Ssum[tid + j * 256] = 0.f; Ssq[tid + j * 256] = 0.f; }
    __syncthreads();
    if (lane < 4) {
#pragma unroll
        for (int nt = 0; nt < 8; nt++) {
            int col = wn * 64 + nt * 8 + lane * 2;
            Ssum[wid * 128 + col]     = ssum[nt * 2 + 0];
            Ssum[wid * 128 + col + 1] = ssum[nt * 2 + 1];
            Ssq [wid * 128 + col]     = ssq[nt * 2 + 0];
            Ssq [wid * 128 + col + 1] = ssq[nt * 2 + 1];
        }
    }
    __syncthreads();
    if (tid < 128) {
        float a = 0.f, b = 0.f;
#pragma unroll
        for (int w = 0; w < 8; w++) { a += Ssum[w * 128 + tid]; b += Ssq[w * 128 + tid]; }
        atomicAdd(&g_stats[tid],       a);
        atomicAdd(&g_stats[128 + tid], b);
    }
}

// ---------------------------------------------------------------------------
// Kernel 3: BatchNorm + ReLU, in place on h
// ---------------------------------------------------------------------------
__global__ void bn_kernel(float* __restrict__ h, int V) {
    __shared__ float ms[128];
    __shared__ float rs[128];
    if (threadIdx.x < 128) {
        float invn = 1.f / (float)V;
        float s  = g_stats[threadIdx.x];
        float sq = g_stats[128 + threadIdx.x];
        float m  = s * invn;
        float var = sq * invn - m * m;
        ms[threadIdx.x] = m;
        rs[threadIdx.x] = rsqrtf(var + 1e-5f);
    }
    __syncthreads();
    size_t total = (size_t)V * 32;
    float4* h4 = reinterpret_cast<float4*>(h);
    for (size_t i = (size_t)blockIdx.x * blockDim.x + threadIdx.x; i < total;
         i += (size_t)gridDim.x * blockDim.x) {
        int c4 = (int)(i & 31) * 4;
        float4 hv = h4[i];
        hv.x = fmaxf((hv.x - ms[c4 + 0]) * rs[c4 + 0], 0.f);
        hv.y = fmaxf((hv.y - ms[c4 + 1]) * rs[c4 + 1], 0.f);
        hv.z = fmaxf((hv.z - ms[c4 + 2]) * rs[c4 + 2], 0.f);
        hv.w = fmaxf((hv.w - ms[c4 + 3]) * rs[c4 + 3], 0.f);
        h4[i] = hv;
    }
}

// ---------------------------------------------------------------------------
// Kernel 4: rel_repr @ w_rel, 4 rel rows per block
// ---------------------------------------------------------------------------
__global__ void relw_kernel(const float* __restrict__ rel,
                            const float* __restrict__ w_rel,
                            float* __restrict__ out, int R) {
    __shared__ float rr[4][128];
    int r0 = blockIdx.x * 4;
    int c = threadIdx.x;
#pragma unroll
    for (int j = 0; j < 4; j++)
        rr[j][c] = (r0 + j < R) ? rel[(size_t)(r0 + j) * DD + c] : 0.f;
    __syncthreads();
    float a0 = 0.f, a1 = 0.f, a2 = 0.f, a3 = 0.f;
#pragma unroll 4
    for (int k = 0; k < 128; k++) {
        float w = __ldg(&w_rel[(size_t)k * DD + c]);
        a0 += rr[0][k] * w;
        a1 += rr[1][k] * w;
        a2 += rr[2][k] * w;
        a3 += rr[3][k] * w;
    }
    if (r0 + 0 < R) out[(size_t)(r0 + 0) * DD + c] = a0;
    if (r0 + 1 < R) out[(size_t)(r0 + 1) * DD + c] = a1;
    if (r0 + 2 < R) out[(size_t)(r0 + 2) * DD + c] = a2;
    if (r0 + 3 < R) out[(size_t)(r0 + 3) * DD + c] = a3;
}

// ---------------------------------------------------------------------------
extern "C" void kernel_launch(void* const* d_in, const int* in_sizes, int n_in,
                              void* d_out, int out_size) {
    const float* x        = (const float*)d_in[0];
    const float* rel      = (const float*)d_in[1];
    const float* enorm    = (const float*)d_in[2];
    const float* in_w     = (const float*)d_in[3];
    const float* out_w    = (const float*)d_in[4];
    const float* loop_w   = (const float*)d_in[5];
    const float* w_rel    = (const float*)d_in[6];
    const float* loop_rel = (const float*)d_in[7];
    const float* bias     = (const float*)d_in[8];
    const int*   src      = (const int*)d_in[9];
    const int*   dst      = (const int*)d_in[10];
    const int*   et       = (const int*)d_in[11];

    int V = in_sizes[0] / DD;
    int R = in_sizes[1] / DD;
    int E = in_sizes[2];
    int half = E / 2;

    float* h    = (float*)d_out;
    float* out2 = h + (size_t)V * DD;

    void* yptr = nullptr; void* sptr = nullptr;
    cudaGetSymbolAddress(&yptr, g_Y);
    cudaGetSymbolAddress(&sptr, g_stats);
    float* Yin  = (float*)yptr;
    float* Yout = Yin + (size_t)V * DD;
    cudaMemsetAsync(yptr, 0, (size_t)2 * V * DD * sizeof(float), 0);
    cudaMemsetAsync(sptr, 0, 2 * DD * sizeof(float), 0);

    cudaFuncSetAttribute(gemm_mma, cudaFuncAttributeMaxDynamicSharedMemorySize,
                         SMEM_GEMM);

    prep_w<<<6, 256>>>(in_w, out_w, loop_w, loop_rel);
    // two passes: per-launch working set (x + half of Y) fits in L2
    edge_kernel<<<(half + 7) / 8, 256>>>(x, rel, enorm, src, dst, et, half, Yin);
    edge_kernel<<<(E - half + 7) / 8, 256>>>(x, rel, enorm + half, src + half,
                                             dst + half, et + half, E - half, Yout);
    gemm_mma<<<(V + 127) / 128, 256, SMEM_GEMM>>>(x, bias, h, V);
    bn_kernel<<<1024, 256>>>(h, V);
    relw_kernel<<<(R + 3) / 4, 128>>>(rel, w_rel, out2, R);
}